// round 14
// baseline (speedup 1.0000x reference)
#include <cuda_runtime.h>
#include <cuda_bf16.h>
#include <math.h>
#include <stdint.h>

#define T_ 30
#define C_ 512
#define N_ 784
#define K_ 64
#define KD_ (K_ * C_)   // 32768
#define NB_ 13          // assign n-tiles per t
#define NPAD_ 832       // 13 * 64, padded n for bf16 a
#define LSS_ 66         // Ls row stride (floats)

// ---------------- device scratch ----------------
__device__ __nv_bfloat16 g_whi[K_ * C_];           // w hi, [k][c]
__device__ __nv_bfloat16 g_wlo[K_ * C_];           // w lo
__device__ __nv_bfloat16 g_ahi[T_ * K_ * NPAD_];   // a' hi, [t][k][n]
__device__ __nv_bfloat16 g_alo[T_ * K_ * NPAD_];   // a' lo
__device__ float g_asump[T_ * NB_ * K_];           // per-block partial asum
__device__ float g_vlad[T_ * K_ * C_];             // CORRECTED vlad [t][k][c] (pre-intra-norm)
__device__ float g_ssp[T_ * K_ * 4];               // per-row sumsq partials (4 c-blocks)

// ---------------- mma.sync helpers (plain sm_80+ PTX) ----------------
__device__ __forceinline__ void ldm_x4(uint32_t* r, uint32_t addr) {
    asm volatile("ldmatrix.sync.aligned.m8n8.x4.shared.b16 {%0,%1,%2,%3}, [%4];"
        : "=r"(r[0]), "=r"(r[1]), "=r"(r[2]), "=r"(r[3]) : "r"(addr));
}
__device__ __forceinline__ void ldm_x4t(uint32_t* r, uint32_t addr) {
    asm volatile("ldmatrix.sync.aligned.m8n8.x4.trans.shared.b16 {%0,%1,%2,%3}, [%4];"
        : "=r"(r[0]), "=r"(r[1]), "=r"(r[2]), "=r"(r[3]) : "r"(addr));
}
__device__ __forceinline__ void mma_bf16(float* d, const uint32_t* a, uint32_t b0, uint32_t b1) {
    asm volatile("mma.sync.aligned.m16n8k16.row.col.f32.bf16.bf16.f32 "
        "{%0,%1,%2,%3}, {%4,%5,%6,%7}, {%8,%9}, {%0,%1,%2,%3};"
        : "+f"(d[0]), "+f"(d[1]), "+f"(d[2]), "+f"(d[3])
        : "r"(a[0]), "r"(a[1]), "r"(a[2]), "r"(a[3]), "r"(b0), "r"(b1));
}
__device__ __forceinline__ void bsplit(float v, unsigned short& h, unsigned short& l) {
    __nv_bfloat16 bh = __float2bfloat16(v);
    float rem = v - __bfloat162float(bh);
    __nv_bfloat16 bl = __float2bfloat16(rem);
    h = *reinterpret_cast<unsigned short*>(&bh);
    l = *reinterpret_cast<unsigned short*>(&bl);
}

// ---------------- pass 0: split W to bf16 hi/lo + zero a tails ----------------
__global__ void prep_kernel(const float* __restrict__ w) {
    int i = blockIdx.x * 256 + threadIdx.x;   // 32768 threads == K_*C_
    unsigned short h, l;
    bsplit(w[i], h, l);
    *(unsigned short*)&g_whi[i] = h;
    *(unsigned short*)&g_wlo[i] = l;
    const int tailN = NPAD_ - N_;             // 48
    const int tot = T_ * K_ * tailN;          // 92160
    for (int j = i; j < tot; j += 32768) {
        int tk = j / tailN, n = N_ + j % tailN;
        g_ahi[(size_t)tk * NPAD_ + n] = __float2bfloat16(0.f);
        g_alo[(size_t)tk * NPAD_ + n] = __float2bfloat16(0.f);
    }
}

// ---------------- pass 1: assign on mma.sync (bf16 split-4), double-buffered (R13 core) ----------------
#define AW_H 0
#define AW_L 9216
#define AX_H 18432
#define AX_L 27648
#define ABUF 36864
#define A_SMEM (2 * ABUF)   // 73728
__global__ __launch_bounds__(128) void assign_kernel(
    const float* __restrict__ x, const float* __restrict__ bias)
{
    extern __shared__ __align__(16) char sbuf[];
    __shared__ float red[128];
    __shared__ float4 red4[4][16];
    __shared__ float invn_s[64], scv[64], rinvs[64], bsm[64];
    float* Ls = (float*)sbuf;                  // overlay on buffer 0 after GEMM

    const int t   = blockIdx.y;
    const int n0  = blockIdx.x * 64;
    const int tid = threadIdx.x;
    const int wid = tid >> 5;
    const int lane = tid & 31;
    const uint32_t sb = (uint32_t)__cvta_generic_to_shared(sbuf);

    if (tid < 64) bsm[tid] = bias[tid];

    float d[8][4];
#pragma unroll
    for (int g = 0; g < 8; g++)
#pragma unroll
        for (int j = 0; j < 4; j++) d[g][j] = 0.f;

    float4 ss4 = make_float4(0.f, 0.f, 0.f, 0.f);
    const float* xt = x + (size_t)t * C_ * N_;
    const int gn = tid & 15;
    const int nn = n0 + gn * 4;
    const bool nv = (nn < N_);

    uint4 wh[4], wl[4];
    float4 xr[8];

#pragma unroll
    for (int it = 0; it < 4; it++) {
        int e = tid + it * 128;
        int k = e >> 3, gc = e & 7;
        size_t src = (size_t)k * 1024 + gc * 16;
        wh[it] = *(const uint4*)((const char*)g_whi + src);
        wl[it] = *(const uint4*)((const char*)g_wlo + src);
    }
#pragma unroll
    for (int it = 0; it < 8; it++) {
        int e = tid + it * 128;
        int c = e >> 4;
        float4 v = make_float4(0.f, 0.f, 0.f, 0.f);
        if (nv) v = *(const float4*)&xt[(size_t)c * N_ + nn];
        ss4.x += v.x * v.x; ss4.y += v.y * v.y; ss4.z += v.z * v.z; ss4.w += v.w * v.w;
        xr[it] = v;
    }
#pragma unroll
    for (int it = 0; it < 4; it++) {
        int e = tid + it * 128;
        int k = e >> 3, gc = e & 7;
        *(uint4*)(sbuf + AW_H + k * 144 + gc * 16) = wh[it];
        *(uint4*)(sbuf + AW_L + k * 144 + gc * 16) = wl[it];
    }
#pragma unroll
    for (int it = 0; it < 8; it++) {
        int e = tid + it * 128;
        int c = e >> 4;
        unsigned short h0,h1,h2,h3, l0,l1,l2,l3;
        bsplit(xr[it].x, h0, l0); bsplit(xr[it].y, h1, l1);
        bsplit(xr[it].z, h2, l2); bsplit(xr[it].w, h3, l3);
        uint2 uh, ul;
        uh.x = h0 | ((uint32_t)h1 << 16); uh.y = h2 | ((uint32_t)h3 << 16);
        ul.x = l0 | ((uint32_t)l1 << 16); ul.y = l2 | ((uint32_t)l3 << 16);
        *(uint2*)(sbuf + AX_H + c * 144 + gn * 8) = uh;
        *(uint2*)(sbuf + AX_L + c * 144 + gn * 8) = ul;
    }
    __syncthreads();

    for (int ch = 0; ch < 8; ch++) {
        const int b = ch & 1;
        const uint32_t bo = (uint32_t)b * ABUF;

        if (ch < 7) {
            const int chp = ch + 1;
#pragma unroll
            for (int it = 0; it < 4; it++) {
                int e = tid + it * 128;
                int k = e >> 3, gc = e & 7;
                size_t src = (size_t)k * 1024 + (size_t)chp * 128 + gc * 16;
                wh[it] = *(const uint4*)((const char*)g_whi + src);
                wl[it] = *(const uint4*)((const char*)g_wlo + src);
            }
#pragma unroll
            for (int it = 0; it < 8; it++) {
                int e = tid + it * 128;
                int c = e >> 4;
                float4 v = make_float4(0.f, 0.f, 0.f, 0.f);
                if (nv) v = *(const float4*)&xt[(size_t)(chp * 64 + c) * N_ + nn];
                ss4.x += v.x * v.x; ss4.y += v.y * v.y; ss4.z += v.z * v.z; ss4.w += v.w * v.w;
                xr[it] = v;
            }
        }

#pragma unroll
        for (int ks = 0; ks < 4; ks++) {
            uint32_t Ah[4], Al[4], Bh[4][4], Bl[4][4];
            {
                uint32_t adr = sb + bo + AW_H + (wid * 16 + (lane & 15)) * 144
                             + ((uint32_t)(ks * 16 + (lane >> 4) * 8)) * 2;
                ldm_x4(Ah, adr);
                ldm_x4(Al, adr + (AW_L - AW_H));
            }
#pragma unroll
            for (int q = 0; q < 4; q++) {
                int c = ks * 16 + ((lane >> 3) & 1) * 8 + (lane & 7);
                int ncol = (2 * q + (lane >> 4)) * 8;
                uint32_t adr = sb + bo + AX_H + c * 144 + (uint32_t)ncol * 2;
                ldm_x4t(Bh[q], adr);
                ldm_x4t(Bl[q], adr + (AX_L - AX_H));
            }
#pragma unroll
            for (int g = 0; g < 8; g++) {
                int bp = g >> 1, hp = (g & 1) * 2;
                mma_bf16(d[g], Ah, Bh[bp][hp], Bh[bp][hp + 1]);
                mma_bf16(d[g], Ah, Bl[bp][hp], Bl[bp][hp + 1]);
                mma_bf16(d[g], Al, Bh[bp][hp], Bh[bp][hp + 1]);
                mma_bf16(d[g], Al, Bl[bp][hp], Bl[bp][hp + 1]);
            }
        }

        if (ch < 7) {
            char* ob = sbuf + (b ^ 1) * ABUF;
#pragma unroll
            for (int it = 0; it < 4; it++) {
                int e = tid + it * 128;
                int k = e >> 3, gc = e & 7;
                *(uint4*)(ob + AW_H + k * 144 + gc * 16) = wh[it];
                *(uint4*)(ob + AW_L + k * 144 + gc * 16) = wl[it];
            }
#pragma unroll
            for (int it = 0; it < 8; it++) {
                int e = tid + it * 128;
                int c = e >> 4;
                unsigned short h0,h1,h2,h3, l0,l1,l2,l3;
                bsplit(xr[it].x, h0, l0); bsplit(xr[it].y, h1, l1);
                bsplit(xr[it].z, h2, l2); bsplit(xr[it].w, h3, l3);
                uint2 uh, ul;
                uh.x = h0 | ((uint32_t)h1 << 16); uh.y = h2 | ((uint32_t)h3 << 16);
                ul.x = l0 | ((uint32_t)l1 << 16); ul.y = l2 | ((uint32_t)l3 << 16);
                *(uint2*)(ob + AX_H + c * 144 + gn * 8) = uh;
                *(uint2*)(ob + AX_L + c * 144 + gn * 8) = ul;
            }
            __syncthreads();
        }
    }

    ss4.x += __shfl_xor_sync(0xffffffff, ss4.x, 16);
    ss4.y += __shfl_xor_sync(0xffffffff, ss4.y, 16);
    ss4.z += __shfl_xor_sync(0xffffffff, ss4.z, 16);
    ss4.w += __shfl_xor_sync(0xffffffff, ss4.w, 16);
    if ((tid & 31) < 16) red4[tid >> 5][tid & 15] = ss4;
    __syncthreads();
    if (tid < 16) {
        float4 a = red4[0][tid], b = red4[1][tid], c = red4[2][tid], dd = red4[3][tid];
        invn_s[tid * 4 + 0] = 1.f / fmaxf(sqrtf(a.x + b.x + c.x + dd.x), 1e-12f);
        invn_s[tid * 4 + 1] = 1.f / fmaxf(sqrtf(a.y + b.y + c.y + dd.y), 1e-12f);
        invn_s[tid * 4 + 2] = 1.f / fmaxf(sqrtf(a.z + b.z + c.z + dd.z), 1e-12f);
        invn_s[tid * 4 + 3] = 1.f / fmaxf(sqrtf(a.w + b.w + c.w + dd.w), 1e-12f);
    }
    __syncthreads();

    {
        int k = wid * 16 + (lane >> 2);
        float bk0 = bsm[k], bk1 = bsm[k + 8];
#pragma unroll
        for (int g = 0; g < 8; g++) {
            int n = g * 8 + (lane & 3) * 2;
            float i0 = invn_s[n], i1 = invn_s[n + 1];
            *(float2*)&Ls[k * LSS_ + n]       = make_float2(d[g][0] * i0 + bk0, d[g][1] * i1 + bk0);
            *(float2*)&Ls[(k + 8) * LSS_ + n] = make_float2(d[g][2] * i0 + bk1, d[g][3] * i1 + bk1);
        }
    }
    __syncthreads();

    const int col  = tid & 63;
    const int half = tid >> 6;
    float m = -1e30f;
#pragma unroll
    for (int kk = 0; kk < 32; kk++) m = fmaxf(m, Ls[(half * 32 + kk) * LSS_ + col]);
    red[half * 64 + col] = m;
    __syncthreads();
    m = fmaxf(red[col], red[64 + col]);
    __syncthreads();
    float s = 0.f;
#pragma unroll
    for (int kk = 0; kk < 32; kk++) {
        float e = __expf(Ls[(half * 32 + kk) * LSS_ + col] - m);
        Ls[(half * 32 + kk) * LSS_ + col] = e;
        s += e;
    }
    red[half * 64 + col] = s;
    __syncthreads();
    const bool valid = (n0 + col < N_);
    float S    = red[col] + red[64 + col];
    float rinv = valid ? (1.f / S) : 0.f;
    if (half == 0) {
        rinvs[col] = rinv;
        scv[col]   = rinv * invn_s[col];
    }
    __syncthreads();

    {
        int k = tid >> 1, h = tid & 1;
        size_t base = (size_t)(t * K_ + k) * NPAD_ + n0 + h * 32;
#pragma unroll
        for (int j = 0; j < 4; j++) {
            unsigned short hh[8], ll[8];
#pragma unroll
            for (int q = 0; q < 8; q++) {
                int n = h * 32 + j * 8 + q;
                float v = Ls[k * LSS_ + n] * scv[n];
                bsplit(v, hh[q], ll[q]);
            }
            uint4 uh, ul;
            uh.x = hh[0] | ((uint32_t)hh[1] << 16); uh.y = hh[2] | ((uint32_t)hh[3] << 16);
            uh.z = hh[4] | ((uint32_t)hh[5] << 16); uh.w = hh[6] | ((uint32_t)hh[7] << 16);
            ul.x = ll[0] | ((uint32_t)ll[1] << 16); ul.y = ll[2] | ((uint32_t)ll[3] << 16);
            ul.z = ll[4] | ((uint32_t)ll[5] << 16); ul.w = ll[6] | ((uint32_t)ll[7] << 16);
            *(uint4*)&g_ahi[base + j * 8] = uh;
            *(uint4*)&g_alo[base + j * 8] = ul;
        }
    }

    if (tid < 64) {
        float as = 0.f;
#pragma unroll 8
        for (int c2 = 0; c2 < 64; c2++) {
            int cix = (c2 + tid) & 63;
            as += Ls[tid * LSS_ + cix] * rinvs[cix];
        }
        g_asump[((size_t)t * NB_ + blockIdx.x) * K_ + tid] = as;
    }
}

// ---------------- pass 2: VLAD GEMM + fused centroid-subtract + row-sumsq partials ----------------
#define VA_HI 0
#define VA_LO 9216
#define VB_HI 18432
#define VB_LO 36864
#define V_SMEM 55296
__global__ __launch_bounds__(256) void vlad_kernel(
    const float* __restrict__ x, const float* __restrict__ cent)
{
    extern __shared__ char sm[];
    __shared__ float s_as[64];
    __shared__ float s_ss[64][4];
    const int t    = blockIdx.y;
    const int c0   = blockIdx.x * 128;
    const int tid  = threadIdx.x;
    const int wid  = tid >> 5;
    const int lane = tid & 31;
    const int wm   = wid & 1;
    const int wn   = wid >> 1;

    uint32_t sb = (uint32_t)__cvta_generic_to_shared(sm);

    // asum per k (sum 13 partials) -> smem
    if (tid < 64) {
        float as = 0.f;
#pragma unroll
        for (int b = 0; b < NB_; b++)
            as += g_asump[((size_t)t * NB_ + b) * K_ + tid];
        s_as[tid] = as;
    }

    float d[8][4];
#pragma unroll
    for (int i = 0; i < 8; i++)
#pragma unroll
        for (int j = 0; j < 4; j++) d[i][j] = 0.f;

    const float* xt = x + (size_t)t * C_ * N_;
    const __nv_bfloat16* aht = g_ahi + (size_t)t * K_ * NPAD_;
    const __nv_bfloat16* alt = g_alo + (size_t)t * K_ * NPAD_;

    {
        const int n0 = 0;
#pragma unroll
        for (int it = 0; it < 4; it++) {
            int e = tid + it * 256;
            int r = e >> 3, g = e & 7;
            int n = n0 + g * 8;
            float4 f0 = make_float4(0.f,0.f,0.f,0.f), f1 = f0;
            if (n < N_) {
                f0 = *(const float4*)&xt[(size_t)(c0 + r) * N_ + n];
                f1 = *(const float4*)&xt[(size_t)(c0 + r) * N_ + n + 4];
            }
            float vv[8] = {f0.x,f0.y,f0.z,f0.w,f1.x,f1.y,f1.z,f1.w};
            unsigned short hh[8], ll[8];
#pragma unroll
            for (int q = 0; q < 8; q++) bsplit(vv[q], hh[q], ll[q]);
            uint4 uh, ul;
            uh.x = hh[0] | ((uint32_t)hh[1] << 16); uh.y = hh[2] | ((uint32_t)hh[3] << 16);
            uh.z = hh[4] | ((uint32_t)hh[5] << 16); uh.w = hh[6] | ((uint32_t)hh[7] << 16);
            ul.x = ll[0] | ((uint32_t)ll[1] << 16); ul.y = ll[2] | ((uint32_t)ll[3] << 16);
            ul.z = ll[4] | ((uint32_t)ll[5] << 16); ul.w = ll[6] | ((uint32_t)ll[7] << 16);
            *(uint4*)(sm + VB_HI + r * 144 + g * 16) = uh;
            *(uint4*)(sm + VB_LO + r * 144 + g * 16) = ul;
        }
#pragma unroll
        for (int it = 0; it < 2; it++) {
            int e = tid + it * 256;
            int k = e >> 3, g = e & 7;
            size_t off = (size_t)k * NPAD_ + g * 8;
            *(uint4*)(sm + VA_HI + k * 144 + g * 16) = *(const uint4*)(aht + off);
            *(uint4*)(sm + VA_LO + k * 144 + g * 16) = *(const uint4*)(alt + off);
        }
    }
    __syncthreads();

    for (int ch = 0; ch < 13; ch++) {
        float4 xp[8];
        uint4  aph[2], apl[2];
        if (ch < 12) {
            const int n0 = (ch + 1) * 64;
#pragma unroll
            for (int it = 0; it < 4; it++) {
                int e = tid + it * 256;
                int r = e >> 3, g = e & 7;
                int n = n0 + g * 8;
                xp[it*2] = make_float4(0.f,0.f,0.f,0.f);
                xp[it*2+1] = make_float4(0.f,0.f,0.f,0.f);
                if (n < N_) {
                    xp[it*2]   = *(const float4*)&xt[(size_t)(c0 + r) * N_ + n];
                    xp[it*2+1] = *(const float4*)&xt[(size_t)(c0 + r) * N_ + n + 4];
                }
            }
#pragma unroll
            for (int it = 0; it < 2; it++) {
                int e = tid + it * 256;
                int k = e >> 3, g = e & 7;
                size_t off = (size_t)k * NPAD_ + n0 + g * 8;
                aph[it] = *(const uint4*)(aht + off);
                apl[it] = *(const uint4*)(alt + off);
            }
        }

#pragma unroll
        for (int ks = 0; ks < 4; ks++) {
            uint32_t Ah[2][4], Al[2][4], Bh[2][4], Bl[2][4];
#pragma unroll
            for (int mt = 0; mt < 2; mt++) {
                int row = wm * 32 + mt * 16 + (lane & 15);
                uint32_t coff = (uint32_t)(ks * 16 + (lane >> 4) * 8) * 2;
                uint32_t adr = sb + VA_HI + row * 144 + coff;
                ldm_x4(Ah[mt], adr);
                ldm_x4(Al[mt], adr + (VA_LO - VA_HI));
            }
#pragma unroll
            for (int bp = 0; bp < 2; bp++) {
                int crow = wn * 32 + bp * 16 + ((lane >> 4) << 3) + (lane & 7);
                uint32_t coff = (uint32_t)(ks * 16 + ((lane >> 3) & 1) * 8) * 2;
                uint32_t adr = sb + VB_HI + crow * 144 + coff;
                ldm_x4(Bh[bp], adr);
                ldm_x4(Bl[bp], adr + (VB_LO - VB_HI));
            }
#pragma unroll
            for (int mt = 0; mt < 2; mt++) {
#pragma unroll
                for (int nt = 0; nt < 4; nt++) {
                    int bp = nt >> 1, hp = (nt & 1) * 2;
                    float* dd = d[mt * 4 + nt];
                    mma_bf16(dd, Ah[mt], Bh[bp][hp], Bh[bp][hp + 1]);
                    mma_bf16(dd, Ah[mt], Bl[bp][hp], Bl[bp][hp + 1]);
                    mma_bf16(dd, Al[mt], Bh[bp][hp], Bh[bp][hp + 1]);
                }
            }
        }

        if (ch < 12) {
            __syncthreads();
#pragma unroll
            for (int it = 0; it < 4; it++) {
                int e = tid + it * 256;
                int r = e >> 3, g = e & 7;
                float4 f0 = xp[it*2], f1 = xp[it*2+1];
                float vv[8] = {f0.x,f0.y,f0.z,f0.w,f1.x,f1.y,f1.z,f1.w};
                unsigned short hh[8], ll[8];
#pragma unroll
                for (int q = 0; q < 8; q++) bsplit(vv[q], hh[q], ll[q]);
                uint4 uh, ul;
                uh.x = hh[0] | ((uint32_t)hh[1] << 16); uh.y = hh[2] | ((uint32_t)hh[3] << 16);
                uh.z = hh[4] | ((uint32_t)hh[5] << 16); uh.w = hh[6] | ((uint32_t)hh[7] << 16);
                ul.x = ll[0] | ((uint32_t)ll[1] << 16); ul.y = ll[2] | ((uint32_t)ll[3] << 16);
                ul.z = ll[4] | ((uint32_t)ll[5] << 16); ul.w = ll[6] | ((uint32_t)ll[7] << 16);
                *(uint4*)(sm + VB_HI + r * 144 + g * 16) = uh;
                *(uint4*)(sm + VB_LO + r * 144 + g * 16) = ul;
            }
#pragma unroll
            for (int it = 0; it < 2; it++) {
                int e = tid + it * 256;
                int k = e >> 3, g = e & 7;
                *(uint4*)(sm + VA_HI + k * 144 + g * 16) = aph[it];
                *(uint4*)(sm + VA_LO + k * 144 + g * 16) = apl[it];
            }
            __syncthreads();
        }
    }

    // ---- fused epilogue: v = D - as*cent, store v, per-row sumsq partials ----
    float ssl[2][2] = {{0.f, 0.f}, {0.f, 0.f}};   // [mt][k / k+8]
#pragma unroll
    for (int mt = 0; mt < 2; mt++) {
        int k0r = wm * 32 + mt * 16 + (lane >> 2);
        float as0 = s_as[k0r], as1 = s_as[k0r + 8];
#pragma unroll
        for (int nt = 0; nt < 4; nt++) {
            float* dd = d[mt * 4 + nt];
            int c = c0 + wn * 32 + nt * 8 + (lane & 3) * 2;
            float2 cw0 = *(const float2*)&cent[(size_t)k0r * C_ + c];
            float2 cw1 = *(const float2*)&cent[(size_t)(k0r + 8) * C_ + c];
            float v00 = dd[0] - as0 * cw0.x, v01 = dd[1] - as0 * cw0.y;
            float v10 = dd[2] - as1 * cw1.x, v11 = dd[3] - as1 * cw1.y;
            *(float2*)&g_vlad[(size_t)(t * K_ + k0r) * C_ + c]     = make_float2(v00, v01);
            *(float2*)&g_vlad[(size_t)(t * K_ + k0r + 8) * C_ + c] = make_float2(v10, v11);
            ssl[mt][0] += v00 * v00 + v01 * v01;
            ssl[mt][1] += v10 * v10 + v11 * v11;
        }
    }
#pragma unroll
    for (int mt = 0; mt < 2; mt++) {
#pragma unroll
        for (int hk = 0; hk < 2; hk++) {
            ssl[mt][hk] += __shfl_xor_sync(0xffffffff, ssl[mt][hk], 1);
            ssl[mt][hk] += __shfl_xor_sync(0xffffffff, ssl[mt][hk], 2);
        }
    }
    if ((lane & 3) == 0) {
        int r = lane >> 2;
#pragma unroll
        for (int mt = 0; mt < 2; mt++) {
            int k = wm * 32 + mt * 16 + r;
            s_ss[k][wn]     = ssl[mt][0];
            s_ss[k + 8][wn] = ssl[mt][1];
        }
    }
    __syncthreads();
    if (tid < 64) {
        float ss = s_ss[tid][0] + s_ss[tid][1] + s_ss[tid][2] + s_ss[tid][3];
        g_ssp[(size_t)(t * K_ + tid) * 4 + blockIdx.x] = ss;
    }
}

// ---------------- pass 3: fused scalars + global normalize + sum over t ----------------
// out[i=k*512+c] = Σ_t v[t][i]·A[t,k],  A = sc·gsc
__global__ __launch_bounds__(256) void finalize_kernel(float* __restrict__ out) {
    __shared__ float sA[T_ * K_];
    __shared__ float sGsc[T_];
    const int tid = threadIdx.x;

    for (int i = tid; i < T_ * K_; i += 256) {
        float ss = g_ssp[(size_t)i * 4 + 0] + g_ssp[(size_t)i * 4 + 1]
                 + g_ssp[(size_t)i * 4 + 2] + g_ssp[(size_t)i * 4 + 3];
        float sc = 1.f / fmaxf(sqrtf(ss), 1e-12f);
        sA[i] = sc;                        // temp: sc; ssn recovered as ss*sc*sc
        red_tmp: ;
        // stash ssn in gssp slot 0? no — recompute below from sc & ss
        // store ssn in shared via second pass: use sGsc scratch later
        // (we fold: ssn = ss * sc * sc)
        // keep ss in register chain by recomputing:
        // handled in the t-loop below
        (void)0;
    }
    __syncthreads();
    if (tid < T_) {
        float s = 0.f;
#pragma unroll 8
        for (int q = 0; q < K_; q++) {
            int i = tid * K_ + q;
            float ss = g_ssp[(size_t)i * 4 + 0] + g_ssp[(size_t)i * 4 + 1]
                     + g_ssp[(size_t)i * 4 + 2] + g_ssp[(size_t)i * 4 + 3];
            float sc = sA[i];
            s += ss * sc * sc;
        }
        sGsc[tid] = 1.f / fmaxf(sqrtf(s), 1e-12f);
    }
    __syncthreads();
    for (int i = tid; i < T_ * K_; i += 256)
        sA[i] = sA[i] * sGsc[i >> 6];
    __syncthreads();

    const int i = blockIdx.x * 256 + tid;
    const int k = i >> 9;
    float s = 0.f;
#pragma unroll
    for (int t = 0; t < T_; t++)
        s += g_vlad[(size_t)t * KD_ + i] * sA[t * K_ + k];
    out[i] = s;
}

// ---------------- launch ----------------
extern "C" void kernel_launch(void* const* d_in, const int* in_sizes, int n_in,
                              void* d_out, int out_size) {
    const float* x1     = (const float*)d_in[0];   // [30,512,28,28]
    const float* cent   = (const float*)d_in[1];   // [64,512]
    const float* conv_w = (const float*)d_in[2];   // [64,512]
    const float* conv_b = (const float*)d_in[3];   // [64]
    float* out = (float*)d_out;                    // [1, 32768]

    cudaFuncSetAttribute(assign_kernel, cudaFuncAttributeMaxDynamicSharedMemorySize, A_SMEM);
    cudaFuncSetAttribute(vlad_kernel,   cudaFuncAttributeMaxDynamicSharedMemorySize, V_SMEM);

    prep_kernel<<<128, 256>>>(conv_w);
    {
        dim3 g(NB_, T_);
        assign_kernel<<<g, 128, A_SMEM>>>(x1, conv_b);
    }
    {
        dim3 g(C_ / 128, T_);
        vlad_kernel<<<g, 256, V_SMEM>>>(x1, cent);
    }
    finalize_kernel<<<KD_ / 256, 256>>>(out);
}

// round 15
// speedup vs baseline: 1.0482x; 1.0482x over previous
#include <cuda_runtime.h>
#include <cuda_bf16.h>
#include <math.h>
#include <stdint.h>

#define T_ 30
#define C_ 512
#define N_ 784
#define K_ 64
#define KD_ (K_ * C_)   // 32768
#define NB_ 13          // assign n-tiles per t
#define NPAD_ 832       // 13 * 64, padded n for bf16 a
#define LSS_ 66         // Ls row stride (floats)

// ---------------- device scratch ----------------
__device__ __nv_bfloat16 g_whi[K_ * C_];           // w hi, [k][c]
__device__ __nv_bfloat16 g_wlo[K_ * C_];           // w lo
__device__ __nv_bfloat16 g_ahi[T_ * K_ * NPAD_];   // a' hi, [t][k][n]
__device__ __nv_bfloat16 g_alo[T_ * K_ * NPAD_];   // a' lo
__device__ float g_asump[T_ * NB_ * K_];           // per-block partial asum
__device__ float g_vlad[T_ * K_ * C_];             // CORRECTED vlad [t][k][c] (pre-intra-norm)
__device__ float g_ssp[T_ * K_ * 4];               // per-row sumsq partials (4 c-blocks)
__device__ float g_A[T_ * K_];                     // final per-row scale sc*gsc

// ---------------- mma.sync helpers (plain sm_80+ PTX) ----------------
__device__ __forceinline__ void ldm_x4(uint32_t* r, uint32_t addr) {
    asm volatile("ldmatrix.sync.aligned.m8n8.x4.shared.b16 {%0,%1,%2,%3}, [%4];"
        : "=r"(r[0]), "=r"(r[1]), "=r"(r[2]), "=r"(r[3]) : "r"(addr));
}
__device__ __forceinline__ void ldm_x4t(uint32_t* r, uint32_t addr) {
    asm volatile("ldmatrix.sync.aligned.m8n8.x4.trans.shared.b16 {%0,%1,%2,%3}, [%4];"
        : "=r"(r[0]), "=r"(r[1]), "=r"(r[2]), "=r"(r[3]) : "r"(addr));
}
__device__ __forceinline__ void mma_bf16(float* d, const uint32_t* a, uint32_t b0, uint32_t b1) {
    asm volatile("mma.sync.aligned.m16n8k16.row.col.f32.bf16.bf16.f32 "
        "{%0,%1,%2,%3}, {%4,%5,%6,%7}, {%8,%9}, {%0,%1,%2,%3};"
        : "+f"(d[0]), "+f"(d[1]), "+f"(d[2]), "+f"(d[3])
        : "r"(a[0]), "r"(a[1]), "r"(a[2]), "r"(a[3]), "r"(b0), "r"(b1));
}
__device__ __forceinline__ void bsplit(float v, unsigned short& h, unsigned short& l) {
    __nv_bfloat16 bh = __float2bfloat16(v);
    float rem = v - __bfloat162float(bh);
    __nv_bfloat16 bl = __float2bfloat16(rem);
    h = *reinterpret_cast<unsigned short*>(&bh);
    l = *reinterpret_cast<unsigned short*>(&bl);
}

// ---------------- pass 0: split W to bf16 hi/lo + zero a tails ----------------
__global__ void prep_kernel(const float* __restrict__ w) {
    int i = blockIdx.x * 256 + threadIdx.x;   // 32768 threads == K_*C_
    unsigned short h, l;
    bsplit(w[i], h, l);
    *(unsigned short*)&g_whi[i] = h;
    *(unsigned short*)&g_wlo[i] = l;
    const int tailN = NPAD_ - N_;             // 48
    const int tot = T_ * K_ * tailN;          // 92160
    for (int j = i; j < tot; j += 32768) {
        int tk = j / tailN, n = N_ + j % tailN;
        g_ahi[(size_t)tk * NPAD_ + n] = __float2bfloat16(0.f);
        g_alo[(size_t)tk * NPAD_ + n] = __float2bfloat16(0.f);
    }
}

// ---------------- pass 1: assign on mma.sync (bf16 split-4), double-buffered ----------------
#define AW_H 0
#define AW_L 9216
#define AX_H 18432
#define AX_L 27648
#define ABUF 36864
#define A_SMEM (2 * ABUF)   // 73728
__global__ __launch_bounds__(128) void assign_kernel(
    const float* __restrict__ x, const float* __restrict__ bias)
{
    extern __shared__ __align__(16) char sbuf[];
    __shared__ float red[128];
    __shared__ float4 red4[4][16];
    __shared__ float invn_s[64], scv[64], rinvs[64], bsm[64];
    float* Ls = (float*)sbuf;                  // overlay on buffer 0 after GEMM

    const int t   = blockIdx.y;
    const int n0  = blockIdx.x * 64;
    const int tid = threadIdx.x;
    const int wid = tid >> 5;
    const int lane = tid & 31;
    const uint32_t sb = (uint32_t)__cvta_generic_to_shared(sbuf);

    if (tid < 64) bsm[tid] = bias[tid];

    float d[8][4];
#pragma unroll
    for (int g = 0; g < 8; g++)
#pragma unroll
        for (int j = 0; j < 4; j++) d[g][j] = 0.f;

    float4 ss4 = make_float4(0.f, 0.f, 0.f, 0.f);
    const float* xt = x + (size_t)t * C_ * N_;
    const int gn = tid & 15;
    const int nn = n0 + gn * 4;
    const bool nv = (nn < N_);

    uint4 wh[4], wl[4];
    float4 xr[8];

#pragma unroll
    for (int it = 0; it < 4; it++) {
        int e = tid + it * 128;
        int k = e >> 3, gc = e & 7;
        size_t src = (size_t)k * 1024 + gc * 16;
        wh[it] = *(const uint4*)((const char*)g_whi + src);
        wl[it] = *(const uint4*)((const char*)g_wlo + src);
    }
#pragma unroll
    for (int it = 0; it < 8; it++) {
        int e = tid + it * 128;
        int c = e >> 4;
        float4 v = make_float4(0.f, 0.f, 0.f, 0.f);
        if (nv) v = *(const float4*)&xt[(size_t)c * N_ + nn];
        ss4.x += v.x * v.x; ss4.y += v.y * v.y; ss4.z += v.z * v.z; ss4.w += v.w * v.w;
        xr[it] = v;
    }
#pragma unroll
    for (int it = 0; it < 4; it++) {
        int e = tid + it * 128;
        int k = e >> 3, gc = e & 7;
        *(uint4*)(sbuf + AW_H + k * 144 + gc * 16) = wh[it];
        *(uint4*)(sbuf + AW_L + k * 144 + gc * 16) = wl[it];
    }
#pragma unroll
    for (int it = 0; it < 8; it++) {
        int e = tid + it * 128;
        int c = e >> 4;
        unsigned short h0,h1,h2,h3, l0,l1,l2,l3;
        bsplit(xr[it].x, h0, l0); bsplit(xr[it].y, h1, l1);
        bsplit(xr[it].z, h2, l2); bsplit(xr[it].w, h3, l3);
        uint2 uh, ul;
        uh.x = h0 | ((uint32_t)h1 << 16); uh.y = h2 | ((uint32_t)h3 << 16);
        ul.x = l0 | ((uint32_t)l1 << 16); ul.y = l2 | ((uint32_t)l3 << 16);
        *(uint2*)(sbuf + AX_H + c * 144 + gn * 8) = uh;
        *(uint2*)(sbuf + AX_L + c * 144 + gn * 8) = ul;
    }
    __syncthreads();

    for (int ch = 0; ch < 8; ch++) {
        const int b = ch & 1;
        const uint32_t bo = (uint32_t)b * ABUF;

        if (ch < 7) {
            const int chp = ch + 1;
#pragma unroll
            for (int it = 0; it < 4; it++) {
                int e = tid + it * 128;
                int k = e >> 3, gc = e & 7;
                size_t src = (size_t)k * 1024 + (size_t)chp * 128 + gc * 16;
                wh[it] = *(const uint4*)((const char*)g_whi + src);
                wl[it] = *(const uint4*)((const char*)g_wlo + src);
            }
#pragma unroll
            for (int it = 0; it < 8; it++) {
                int e = tid + it * 128;
                int c = e >> 4;
                float4 v = make_float4(0.f, 0.f, 0.f, 0.f);
                if (nv) v = *(const float4*)&xt[(size_t)(chp * 64 + c) * N_ + nn];
                ss4.x += v.x * v.x; ss4.y += v.y * v.y; ss4.z += v.z * v.z; ss4.w += v.w * v.w;
                xr[it] = v;
            }
        }

#pragma unroll
        for (int ks = 0; ks < 4; ks++) {
            uint32_t Ah[4], Al[4], Bh[4][4], Bl[4][4];
            {
                uint32_t adr = sb + bo + AW_H + (wid * 16 + (lane & 15)) * 144
                             + ((uint32_t)(ks * 16 + (lane >> 4) * 8)) * 2;
                ldm_x4(Ah, adr);
                ldm_x4(Al, adr + (AW_L - AW_H));
            }
#pragma unroll
            for (int q = 0; q < 4; q++) {
                int c = ks * 16 + ((lane >> 3) & 1) * 8 + (lane & 7);
                int ncol = (2 * q + (lane >> 4)) * 8;
                uint32_t adr = sb + bo + AX_H + c * 144 + (uint32_t)ncol * 2;
                ldm_x4t(Bh[q], adr);
                ldm_x4t(Bl[q], adr + (AX_L - AX_H));
            }
#pragma unroll
            for (int g = 0; g < 8; g++) {
                int bp = g >> 1, hp = (g & 1) * 2;
                mma_bf16(d[g], Ah, Bh[bp][hp], Bh[bp][hp + 1]);
                mma_bf16(d[g], Ah, Bl[bp][hp], Bl[bp][hp + 1]);
                mma_bf16(d[g], Al, Bh[bp][hp], Bh[bp][hp + 1]);
                mma_bf16(d[g], Al, Bl[bp][hp], Bl[bp][hp + 1]);
            }
        }

        if (ch < 7) {
            char* ob = sbuf + (b ^ 1) * ABUF;
#pragma unroll
            for (int it = 0; it < 4; it++) {
                int e = tid + it * 128;
                int k = e >> 3, gc = e & 7;
                *(uint4*)(ob + AW_H + k * 144 + gc * 16) = wh[it];
                *(uint4*)(ob + AW_L + k * 144 + gc * 16) = wl[it];
            }
#pragma unroll
            for (int it = 0; it < 8; it++) {
                int e = tid + it * 128;
                int c = e >> 4;
                unsigned short h0,h1,h2,h3, l0,l1,l2,l3;
                bsplit(xr[it].x, h0, l0); bsplit(xr[it].y, h1, l1);
                bsplit(xr[it].z, h2, l2); bsplit(xr[it].w, h3, l3);
                uint2 uh, ul;
                uh.x = h0 | ((uint32_t)h1 << 16); uh.y = h2 | ((uint32_t)h3 << 16);
                ul.x = l0 | ((uint32_t)l1 << 16); ul.y = l2 | ((uint32_t)l3 << 16);
                *(uint2*)(ob + AX_H + c * 144 + gn * 8) = uh;
                *(uint2*)(ob + AX_L + c * 144 + gn * 8) = ul;
            }
            __syncthreads();
        }
    }

    ss4.x += __shfl_xor_sync(0xffffffff, ss4.x, 16);
    ss4.y += __shfl_xor_sync(0xffffffff, ss4.y, 16);
    ss4.z += __shfl_xor_sync(0xffffffff, ss4.z, 16);
    ss4.w += __shfl_xor_sync(0xffffffff, ss4.w, 16);
    if ((tid & 31) < 16) red4[tid >> 5][tid & 15] = ss4;
    __syncthreads();
    if (tid < 16) {
        float4 a = red4[0][tid], b = red4[1][tid], c = red4[2][tid], dd = red4[3][tid];
        invn_s[tid * 4 + 0] = 1.f / fmaxf(sqrtf(a.x + b.x + c.x + dd.x), 1e-12f);
        invn_s[tid * 4 + 1] = 1.f / fmaxf(sqrtf(a.y + b.y + c.y + dd.y), 1e-12f);
        invn_s[tid * 4 + 2] = 1.f / fmaxf(sqrtf(a.z + b.z + c.z + dd.z), 1e-12f);
        invn_s[tid * 4 + 3] = 1.f / fmaxf(sqrtf(a.w + b.w + c.w + dd.w), 1e-12f);
    }
    __syncthreads();

    {
        int k = wid * 16 + (lane >> 2);
        float bk0 = bsm[k], bk1 = bsm[k + 8];
#pragma unroll
        for (int g = 0; g < 8; g++) {
            int n = g * 8 + (lane & 3) * 2;
            float i0 = invn_s[n], i1 = invn_s[n + 1];
            *(float2*)&Ls[k * LSS_ + n]       = make_float2(d[g][0] * i0 + bk0, d[g][1] * i1 + bk0);
            *(float2*)&Ls[(k + 8) * LSS_ + n] = make_float2(d[g][2] * i0 + bk1, d[g][3] * i1 + bk1);
        }
    }
    __syncthreads();

    const int col  = tid & 63;
    const int half = tid >> 6;
    float m = -1e30f;
#pragma unroll
    for (int kk = 0; kk < 32; kk++) m = fmaxf(m, Ls[(half * 32 + kk) * LSS_ + col]);
    red[half * 64 + col] = m;
    __syncthreads();
    m = fmaxf(red[col], red[64 + col]);
    __syncthreads();
    float s = 0.f;
#pragma unroll
    for (int kk = 0; kk < 32; kk++) {
        float e = __expf(Ls[(half * 32 + kk) * LSS_ + col] - m);
        Ls[(half * 32 + kk) * LSS_ + col] = e;
        s += e;
    }
    red[half * 64 + col] = s;
    __syncthreads();
    const bool valid = (n0 + col < N_);
    float S    = red[col] + red[64 + col];
    float rinv = valid ? (1.f / S) : 0.f;
    if (half == 0) {
        rinvs[col] = rinv;
        scv[col]   = rinv * invn_s[col];
    }
    __syncthreads();

    {
        int k = tid >> 1, h = tid & 1;
        size_t base = (size_t)(t * K_ + k) * NPAD_ + n0 + h * 32;
#pragma unroll
        for (int j = 0; j < 4; j++) {
            unsigned short hh[8], ll[8];
#pragma unroll
            for (int q = 0; q < 8; q++) {
                int n = h * 32 + j * 8 + q;
                float v = Ls[k * LSS_ + n] * scv[n];
                bsplit(v, hh[q], ll[q]);
            }
            uint4 uh, ul;
            uh.x = hh[0] | ((uint32_t)hh[1] << 16); uh.y = hh[2] | ((uint32_t)hh[3] << 16);
            uh.z = hh[4] | ((uint32_t)hh[5] << 16); uh.w = hh[6] | ((uint32_t)hh[7] << 16);
            ul.x = ll[0] | ((uint32_t)ll[1] << 16); ul.y = ll[2] | ((uint32_t)ll[3] << 16);
            ul.z = ll[4] | ((uint32_t)ll[5] << 16); ul.w = ll[6] | ((uint32_t)ll[7] << 16);
            *(uint4*)&g_ahi[base + j * 8] = uh;
            *(uint4*)&g_alo[base + j * 8] = ul;
        }
    }

    if (tid < 64) {
        float as = 0.f;
#pragma unroll 8
        for (int c2 = 0; c2 < 64; c2++) {
            int cix = (c2 + tid) & 63;
            as += Ls[tid * LSS_ + cix] * rinvs[cix];
        }
        g_asump[((size_t)t * NB_ + blockIdx.x) * K_ + tid] = as;
    }
}

// ---------------- pass 2: VLAD GEMM + fused centroid-subtract + row-sumsq partials ----------------
#define VA_HI 0
#define VA_LO 9216
#define VB_HI 18432
#define VB_LO 36864
#define V_SMEM 55296
__global__ __launch_bounds__(256) void vlad_kernel(
    const float* __restrict__ x, const float* __restrict__ cent)
{
    extern __shared__ char sm[];
    __shared__ float s_as[64];
    __shared__ float s_ss[64][4];
    const int t    = blockIdx.y;
    const int c0   = blockIdx.x * 128;
    const int tid  = threadIdx.x;
    const int wid  = tid >> 5;
    const int lane = tid & 31;
    const int wm   = wid & 1;
    const int wn   = wid >> 1;

    uint32_t sb = (uint32_t)__cvta_generic_to_shared(sm);

    if (tid < 64) {
        float as = 0.f;
#pragma unroll
        for (int b = 0; b < NB_; b++)
            as += g_asump[((size_t)t * NB_ + b) * K_ + tid];
        s_as[tid] = as;
    }

    float d[8][4];
#pragma unroll
    for (int i = 0; i < 8; i++)
#pragma unroll
        for (int j = 0; j < 4; j++) d[i][j] = 0.f;

    const float* xt = x + (size_t)t * C_ * N_;
    const __nv_bfloat16* aht = g_ahi + (size_t)t * K_ * NPAD_;
    const __nv_bfloat16* alt = g_alo + (size_t)t * K_ * NPAD_;

    {
#pragma unroll
        for (int it = 0; it < 4; it++) {
            int e = tid + it * 256;
            int r = e >> 3, g = e & 7;
            int n = g * 8;
            float4 f0 = make_float4(0.f,0.f,0.f,0.f), f1 = f0;
            if (n < N_) {
                f0 = *(const float4*)&xt[(size_t)(c0 + r) * N_ + n];
                f1 = *(const float4*)&xt[(size_t)(c0 + r) * N_ + n + 4];
            }
            float vv[8] = {f0.x,f0.y,f0.z,f0.w,f1.x,f1.y,f1.z,f1.w};
            unsigned short hh[8], ll[8];
#pragma unroll
            for (int q = 0; q < 8; q++) bsplit(vv[q], hh[q], ll[q]);
            uint4 uh, ul;
            uh.x = hh[0] | ((uint32_t)hh[1] << 16); uh.y = hh[2] | ((uint32_t)hh[3] << 16);
            uh.z = hh[4] | ((uint32_t)hh[5] << 16); uh.w = hh[6] | ((uint32_t)hh[7] << 16);
            ul.x = ll[0] | ((uint32_t)ll[1] << 16); ul.y = ll[2] | ((uint32_t)ll[3] << 16);
            ul.z = ll[4] | ((uint32_t)ll[5] << 16); ul.w = ll[6] | ((uint32_t)ll[7] << 16);
            *(uint4*)(sm + VB_HI + r * 144 + g * 16) = uh;
            *(uint4*)(sm + VB_LO + r * 144 + g * 16) = ul;
        }
#pragma unroll
        for (int it = 0; it < 2; it++) {
            int e = tid + it * 256;
            int k = e >> 3, g = e & 7;
            size_t off = (size_t)k * NPAD_ + g * 8;
            *(uint4*)(sm + VA_HI + k * 144 + g * 16) = *(const uint4*)(aht + off);
            *(uint4*)(sm + VA_LO + k * 144 + g * 16) = *(const uint4*)(alt + off);
        }
    }
    __syncthreads();

    for (int ch = 0; ch < 13; ch++) {
        float4 xp[8];
        uint4  aph[2], apl[2];
        if (ch < 12) {
            const int n0 = (ch + 1) * 64;
#pragma unroll
            for (int it = 0; it < 4; it++) {
                int e = tid + it * 256;
                int r = e >> 3, g = e & 7;
                int n = n0 + g * 8;
                xp[it*2] = make_float4(0.f,0.f,0.f,0.f);
                xp[it*2+1] = make_float4(0.f,0.f,0.f,0.f);
                if (n < N_) {
                    xp[it*2]   = *(const float4*)&xt[(size_t)(c0 + r) * N_ + n];
                    xp[it*2+1] = *(const float4*)&xt[(size_t)(c0 + r) * N_ + n + 4];
                }
            }
#pragma unroll
            for (int it = 0; it < 2; it++) {
                int e = tid + it * 256;
                int k = e >> 3, g = e & 7;
                size_t off = (size_t)k * NPAD_ + n0 + g * 8;
                aph[it] = *(const uint4*)(aht + off);
                apl[it] = *(const uint4*)(alt + off);
            }
        }

#pragma unroll
        for (int ks = 0; ks < 4; ks++) {
            uint32_t Ah[2][4], Al[2][4], Bh[2][4], Bl[2][4];
#pragma unroll
            for (int mt = 0; mt < 2; mt++) {
                int row = wm * 32 + mt * 16 + (lane & 15);
                uint32_t coff = (uint32_t)(ks * 16 + (lane >> 4) * 8) * 2;
                uint32_t adr = sb + VA_HI + row * 144 + coff;
                ldm_x4(Ah[mt], adr);
                ldm_x4(Al[mt], adr + (VA_LO - VA_HI));
            }
#pragma unroll
            for (int bp = 0; bp < 2; bp++) {
                int crow = wn * 32 + bp * 16 + ((lane >> 4) << 3) + (lane & 7);
                uint32_t coff = (uint32_t)(ks * 16 + ((lane >> 3) & 1) * 8) * 2;
                uint32_t adr = sb + VB_HI + crow * 144 + coff;
                ldm_x4(Bh[bp], adr);
                ldm_x4(Bl[bp], adr + (VB_LO - VB_HI));
            }
#pragma unroll
            for (int mt = 0; mt < 2; mt++) {
#pragma unroll
                for (int nt = 0; nt < 4; nt++) {
                    int bp = nt >> 1, hp = (nt & 1) * 2;
                    float* dd = d[mt * 4 + nt];
                    mma_bf16(dd, Ah[mt], Bh[bp][hp], Bh[bp][hp + 1]);
                    mma_bf16(dd, Ah[mt], Bl[bp][hp], Bl[bp][hp + 1]);
                    mma_bf16(dd, Al[mt], Bh[bp][hp], Bh[bp][hp + 1]);
                }
            }
        }

        if (ch < 12) {
            __syncthreads();
#pragma unroll
            for (int it = 0; it < 4; it++) {
                int e = tid + it * 256;
                int r = e >> 3, g = e & 7;
                float4 f0 = xp[it*2], f1 = xp[it*2+1];
                float vv[8] = {f0.x,f0.y,f0.z,f0.w,f1.x,f1.y,f1.z,f1.w};
                unsigned short hh[8], ll[8];
#pragma unroll
                for (int q = 0; q < 8; q++) bsplit(vv[q], hh[q], ll[q]);
                uint4 uh, ul;
                uh.x = hh[0] | ((uint32_t)hh[1] << 16); uh.y = hh[2] | ((uint32_t)hh[3] << 16);
                uh.z = hh[4] | ((uint32_t)hh[5] << 16); uh.w = hh[6] | ((uint32_t)hh[7] << 16);
                ul.x = ll[0] | ((uint32_t)ll[1] << 16); ul.y = ll[2] | ((uint32_t)ll[3] << 16);
                ul.z = ll[4] | ((uint32_t)ll[5] << 16); ul.w = ll[6] | ((uint32_t)ll[7] << 16);
                *(uint4*)(sm + VB_HI + r * 144 + g * 16) = uh;
                *(uint4*)(sm + VB_LO + r * 144 + g * 16) = ul;
            }
#pragma unroll
            for (int it = 0; it < 2; it++) {
                int e = tid + it * 256;
                int k = e >> 3, g = e & 7;
                *(uint4*)(sm + VA_HI + k * 144 + g * 16) = aph[it];
                *(uint4*)(sm + VA_LO + k * 144 + g * 16) = apl[it];
            }
            __syncthreads();
        }
    }

    // ---- fused epilogue: v = D - as*cent, store v, per-row sumsq partials ----
    float ssl[2][2] = {{0.f, 0.f}, {0.f, 0.f}};
#pragma unroll
    for (int mt = 0; mt < 2; mt++) {
        int k0r = wm * 32 + mt * 16 + (lane >> 2);
        float as0 = s_as[k0r], as1 = s_as[k0r + 8];
#pragma unroll
        for (int nt = 0; nt < 4; nt++) {
            float* dd = d[mt * 4 + nt];
            int c = c0 + wn * 32 + nt * 8 + (lane & 3) * 2;
            float2 cw0 = *(const float2*)&cent[(size_t)k0r * C_ + c];
            float2 cw1 = *(const float2*)&cent[(size_t)(k0r + 8) * C_ + c];
            float v00 = dd[0] - as0 * cw0.x, v01 = dd[1] - as0 * cw0.y;
            float v10 = dd[2] - as1 * cw1.x, v11 = dd[3] - as1 * cw1.y;
            *(float2*)&g_vlad[(size_t)(t * K_ + k0r) * C_ + c]     = make_float2(v00, v01);
            *(float2*)&g_vlad[(size_t)(t * K_ + k0r + 8) * C_ + c] = make_float2(v10, v11);
            ssl[mt][0] += v00 * v00 + v01 * v01;
            ssl[mt][1] += v10 * v10 + v11 * v11;
        }
    }
#pragma unroll
    for (int mt = 0; mt < 2; mt++) {
#pragma unroll
        for (int hk = 0; hk < 2; hk++) {
            ssl[mt][hk] += __shfl_xor_sync(0xffffffff, ssl[mt][hk], 1);
            ssl[mt][hk] += __shfl_xor_sync(0xffffffff, ssl[mt][hk], 2);
        }
    }
    if ((lane & 3) == 0) {
        int r = lane >> 2;
#pragma unroll
        for (int mt = 0; mt < 2; mt++) {
            int k = wm * 32 + mt * 16 + r;
            s_ss[k][wn]     = ssl[mt][0];
            s_ss[k + 8][wn] = ssl[mt][1];
        }
    }
    __syncthreads();
    if (tid < 64) {
        float ss = s_ss[tid][0] + s_ss[tid][1] + s_ss[tid][2] + s_ss[tid][3];
        g_ssp[(size_t)(t * K_ + tid) * 4 + blockIdx.x] = ss;
    }
}

// ---------------- pass 3: tiny scalar kernel (1 block): A[t,k] = sc*gsc ----------------
__global__ __launch_bounds__(256) void scalars_kernel() {
    __shared__ float sSc[T_ * K_];
    __shared__ float sSsn[T_ * K_];
    __shared__ float sGsc[T_];
    const int tid = threadIdx.x;
    for (int i = tid; i < T_ * K_; i += 256) {
        float4 p = *(const float4*)&g_ssp[(size_t)i * 4];
        float ss = p.x + p.y + p.z + p.w;
        float sc = 1.f / fmaxf(sqrtf(ss), 1e-12f);
        sSc[i]  = sc;
        sSsn[i] = ss * sc * sc;
    }
    __syncthreads();
    if (tid < T_) {
        float s = 0.f;
#pragma unroll 8
        for (int q = 0; q < K_; q++) s += sSsn[tid * K_ + q];
        sGsc[tid] = 1.f / fmaxf(sqrtf(s), 1e-12f);
    }
    __syncthreads();
    for (int i = tid; i < T_ * K_; i += 256)
        g_A[i] = sSc[i] * sGsc[i >> 6];
}

// ---------------- pass 4: apply scales + sum over t ----------------
__global__ __launch_bounds__(256) void finalize_kernel(float* __restrict__ out) {
    __shared__ float sA[T_ * K_];
    const int tid = threadIdx.x;
    for (int i = tid; i < T_ * K_; i += 256) sA[i] = g_A[i];
    __syncthreads();
    const int i = blockIdx.x * 256 + tid;
    const int k = i >> 9;
    float s = 0.f;
#pragma unroll
    for (int t = 0; t < T_; t++)
        s += g_vlad[(size_t)t * KD_ + i] * sA[t * K_ + k];
    out[i] = s;
}

// ---------------- launch ----------------
extern "C" void kernel_launch(void* const* d_in, const int* in_sizes, int n_in,
                              void* d_out, int out_size) {
    const float* x1     = (const float*)d_in[0];   // [30,512,28,28]
    const float* cent   = (const float*)d_in[1];   // [64,512]
    const float* conv_w = (const float*)d_in[2];   // [64,512]
    const float* conv_b = (const float*)d_in[3];   // [64]
    float* out = (float*)d_out;                    // [1, 32768]

    cudaFuncSetAttribute(assign_kernel, cudaFuncAttributeMaxDynamicSharedMemorySize, A_SMEM);
    cudaFuncSetAttribute(vlad_kernel,   cudaFuncAttributeMaxDynamicSharedMemorySize, V_SMEM);

    prep_kernel<<<128, 256>>>(conv_w);
    {
        dim3 g(NB_, T_);
        assign_kernel<<<g, 128, A_SMEM>>>(x1, conv_b);
    }
    {
        dim3 g(C_ / 128, T_);
        vlad_kernel<<<g, 256, V_SMEM>>>(x1, cent);
    }
    scalars_kernel<<<1, 256>>>();
    finalize_kernel<<<KD_ / 256, 256>>>(out);
}

// round 16
// speedup vs baseline: 1.1195x; 1.0680x over previous
#include <cuda_runtime.h>
#include <cuda_bf16.h>
#include <math.h>
#include <stdint.h>

#define T_ 30
#define C_ 512
#define N_ 784
#define K_ 64
#define KD_ (K_ * C_)   // 32768
#define NB_ 13          // assign n-tiles per t
#define NPAD_ 832       // 13 * 64, padded n for bf16 a
#define LSS_ 66         // Ls row stride (floats)

// ---------------- device scratch ----------------
__device__ __nv_bfloat16 g_whi[K_ * C_];           // w hi, [k][c]
__device__ __nv_bfloat16 g_wlo[K_ * C_];           // w lo
__device__ __nv_bfloat16 g_ahi[T_ * K_ * NPAD_];   // a' hi, [t][k][n]
__device__ __nv_bfloat16 g_alo[T_ * K_ * NPAD_];   // a' lo
__device__ float g_asump[T_ * NB_ * K_];           // per-block partial asum
__device__ float g_vlad[T_ * K_ * C_];             // CORRECTED vlad [t][k][c] (pre-intra-norm)
__device__ float g_ssp[T_ * K_ * 4];               // per-row sumsq partials (4 c-blocks)

// ---------------- mma.sync helpers (plain sm_80+ PTX) ----------------
__device__ __forceinline__ void ldm_x4(uint32_t* r, uint32_t addr) {
    asm volatile("ldmatrix.sync.aligned.m8n8.x4.shared.b16 {%0,%1,%2,%3}, [%4];"
        : "=r"(r[0]), "=r"(r[1]), "=r"(r[2]), "=r"(r[3]) : "r"(addr));
}
__device__ __forceinline__ void ldm_x4t(uint32_t* r, uint32_t addr) {
    asm volatile("ldmatrix.sync.aligned.m8n8.x4.trans.shared.b16 {%0,%1,%2,%3}, [%4];"
        : "=r"(r[0]), "=r"(r[1]), "=r"(r[2]), "=r"(r[3]) : "r"(addr));
}
__device__ __forceinline__ void mma_bf16(float* d, const uint32_t* a, uint32_t b0, uint32_t b1) {
    asm volatile("mma.sync.aligned.m16n8k16.row.col.f32.bf16.bf16.f32 "
        "{%0,%1,%2,%3}, {%4,%5,%6,%7}, {%8,%9}, {%0,%1,%2,%3};"
        : "+f"(d[0]), "+f"(d[1]), "+f"(d[2]), "+f"(d[3])
        : "r"(a[0]), "r"(a[1]), "r"(a[2]), "r"(a[3]), "r"(b0), "r"(b1));
}
__device__ __forceinline__ void bsplit(float v, unsigned short& h, unsigned short& l) {
    __nv_bfloat16 bh = __float2bfloat16(v);
    float rem = v - __bfloat162float(bh);
    __nv_bfloat16 bl = __float2bfloat16(rem);
    h = *reinterpret_cast<unsigned short*>(&bh);
    l = *reinterpret_cast<unsigned short*>(&bl);
}

// ---------------- pass 0: split W to bf16 hi/lo + zero a tails ----------------
__global__ void prep_kernel(const float* __restrict__ w) {
    int i = blockIdx.x * 256 + threadIdx.x;   // 32768 threads == K_*C_
    unsigned short h, l;
    bsplit(w[i], h, l);
    *(unsigned short*)&g_whi[i] = h;
    *(unsigned short*)&g_wlo[i] = l;
    const int tailN = NPAD_ - N_;             // 48
    const int tot = T_ * K_ * tailN;          // 92160
    for (int j = i; j < tot; j += 32768) {
        int tk = j / tailN, n = N_ + j % tailN;
        g_ahi[(size_t)tk * NPAD_ + n] = __float2bfloat16(0.f);
        g_alo[(size_t)tk * NPAD_ + n] = __float2bfloat16(0.f);
    }
}

// ---------------- pass 1: assign on mma.sync (bf16 split-4), double-buffered ----------------
#define AW_H 0
#define AW_L 9216
#define AX_H 18432
#define AX_L 27648
#define ABUF 36864
#define A_SMEM (2 * ABUF)   // 73728
__global__ __launch_bounds__(128) void assign_kernel(
    const float* __restrict__ x, const float* __restrict__ bias)
{
    extern __shared__ __align__(16) char sbuf[];
    __shared__ float red[128];
    __shared__ float4 red4[4][16];
    __shared__ float invn_s[64], scv[64], rinvs[64], bsm[64];
    float* Ls = (float*)sbuf;                  // overlay on buffer 0 after GEMM

    const int t   = blockIdx.y;
    const int n0  = blockIdx.x * 64;
    const int tid = threadIdx.x;
    const int wid = tid >> 5;
    const int lane = tid & 31;
    const uint32_t sb = (uint32_t)__cvta_generic_to_shared(sbuf);

    if (tid < 64) bsm[tid] = bias[tid];

    float d[8][4];
#pragma unroll
    for (int g = 0; g < 8; g++)
#pragma unroll
        for (int j = 0; j < 4; j++) d[g][j] = 0.f;

    float4 ss4 = make_float4(0.f, 0.f, 0.f, 0.f);
    const float* xt = x + (size_t)t * C_ * N_;
    const int gn = tid & 15;
    const int nn = n0 + gn * 4;
    const bool nv = (nn < N_);

    uint4 wh[4], wl[4];
    float4 xr[8];

#pragma unroll
    for (int it = 0; it < 4; it++) {
        int e = tid + it * 128;
        int k = e >> 3, gc = e & 7;
        size_t src = (size_t)k * 1024 + gc * 16;
        wh[it] = *(const uint4*)((const char*)g_whi + src);
        wl[it] = *(const uint4*)((const char*)g_wlo + src);
    }
#pragma unroll
    for (int it = 0; it < 8; it++) {
        int e = tid + it * 128;
        int c = e >> 4;
        float4 v = make_float4(0.f, 0.f, 0.f, 0.f);
        if (nv) v = *(const float4*)&xt[(size_t)c * N_ + nn];
        ss4.x += v.x * v.x; ss4.y += v.y * v.y; ss4.z += v.z * v.z; ss4.w += v.w * v.w;
        xr[it] = v;
    }
#pragma unroll
    for (int it = 0; it < 4; it++) {
        int e = tid + it * 128;
        int k = e >> 3, gc = e & 7;
        *(uint4*)(sbuf + AW_H + k * 144 + gc * 16) = wh[it];
        *(uint4*)(sbuf + AW_L + k * 144 + gc * 16) = wl[it];
    }
#pragma unroll
    for (int it = 0; it < 8; it++) {
        int e = tid + it * 128;
        int c = e >> 4;
        unsigned short h0,h1,h2,h3, l0,l1,l2,l3;
        bsplit(xr[it].x, h0, l0); bsplit(xr[it].y, h1, l1);
        bsplit(xr[it].z, h2, l2); bsplit(xr[it].w, h3, l3);
        uint2 uh, ul;
        uh.x = h0 | ((uint32_t)h1 << 16); uh.y = h2 | ((uint32_t)h3 << 16);
        ul.x = l0 | ((uint32_t)l1 << 16); ul.y = l2 | ((uint32_t)l3 << 16);
        *(uint2*)(sbuf + AX_H + c * 144 + gn * 8) = uh;
        *(uint2*)(sbuf + AX_L + c * 144 + gn * 8) = ul;
    }
    __syncthreads();

    for (int ch = 0; ch < 8; ch++) {
        const int b = ch & 1;
        const uint32_t bo = (uint32_t)b * ABUF;

        if (ch < 7) {
            const int chp = ch + 1;
#pragma unroll
            for (int it = 0; it < 4; it++) {
                int e = tid + it * 128;
                int k = e >> 3, gc = e & 7;
                size_t src = (size_t)k * 1024 + (size_t)chp * 128 + gc * 16;
                wh[it] = *(const uint4*)((const char*)g_whi + src);
                wl[it] = *(const uint4*)((const char*)g_wlo + src);
            }
#pragma unroll
            for (int it = 0; it < 8; it++) {
                int e = tid + it * 128;
                int c = e >> 4;
                float4 v = make_float4(0.f, 0.f, 0.f, 0.f);
                if (nv) v = *(const float4*)&xt[(size_t)(chp * 64 + c) * N_ + nn];
                ss4.x += v.x * v.x; ss4.y += v.y * v.y; ss4.z += v.z * v.z; ss4.w += v.w * v.w;
                xr[it] = v;
            }
        }

#pragma unroll
        for (int ks = 0; ks < 4; ks++) {
            uint32_t Ah[4], Al[4], Bh[4][4], Bl[4][4];
            {
                uint32_t adr = sb + bo + AW_H + (wid * 16 + (lane & 15)) * 144
                             + ((uint32_t)(ks * 16 + (lane >> 4) * 8)) * 2;
                ldm_x4(Ah, adr);
                ldm_x4(Al, adr + (AW_L - AW_H));
            }
#pragma unroll
            for (int q = 0; q < 4; q++) {
                int c = ks * 16 + ((lane >> 3) & 1) * 8 + (lane & 7);
                int ncol = (2 * q + (lane >> 4)) * 8;
                uint32_t adr = sb + bo + AX_H + c * 144 + (uint32_t)ncol * 2;
                ldm_x4t(Bh[q], adr);
                ldm_x4t(Bl[q], adr + (AX_L - AX_H));
            }
#pragma unroll
            for (int g = 0; g < 8; g++) {
                int bp = g >> 1, hp = (g & 1) * 2;
                mma_bf16(d[g], Ah, Bh[bp][hp], Bh[bp][hp + 1]);
                mma_bf16(d[g], Ah, Bl[bp][hp], Bl[bp][hp + 1]);
                mma_bf16(d[g], Al, Bh[bp][hp], Bh[bp][hp + 1]);
                mma_bf16(d[g], Al, Bl[bp][hp], Bl[bp][hp + 1]);
            }
        }

        if (ch < 7) {
            char* ob = sbuf + (b ^ 1) * ABUF;
#pragma unroll
            for (int it = 0; it < 4; it++) {
                int e = tid + it * 128;
                int k = e >> 3, gc = e & 7;
                *(uint4*)(ob + AW_H + k * 144 + gc * 16) = wh[it];
                *(uint4*)(ob + AW_L + k * 144 + gc * 16) = wl[it];
            }
#pragma unroll
            for (int it = 0; it < 8; it++) {
                int e = tid + it * 128;
                int c = e >> 4;
                unsigned short h0,h1,h2,h3, l0,l1,l2,l3;
                bsplit(xr[it].x, h0, l0); bsplit(xr[it].y, h1, l1);
                bsplit(xr[it].z, h2, l2); bsplit(xr[it].w, h3, l3);
                uint2 uh, ul;
                uh.x = h0 | ((uint32_t)h1 << 16); uh.y = h2 | ((uint32_t)h3 << 16);
                ul.x = l0 | ((uint32_t)l1 << 16); ul.y = l2 | ((uint32_t)l3 << 16);
                *(uint2*)(ob + AX_H + c * 144 + gn * 8) = uh;
                *(uint2*)(ob + AX_L + c * 144 + gn * 8) = ul;
            }
            __syncthreads();
        }
    }

    ss4.x += __shfl_xor_sync(0xffffffff, ss4.x, 16);
    ss4.y += __shfl_xor_sync(0xffffffff, ss4.y, 16);
    ss4.z += __shfl_xor_sync(0xffffffff, ss4.z, 16);
    ss4.w += __shfl_xor_sync(0xffffffff, ss4.w, 16);
    if ((tid & 31) < 16) red4[tid >> 5][tid & 15] = ss4;
    __syncthreads();
    if (tid < 16) {
        float4 a = red4[0][tid], b = red4[1][tid], c = red4[2][tid], dd = red4[3][tid];
        invn_s[tid * 4 + 0] = 1.f / fmaxf(sqrtf(a.x + b.x + c.x + dd.x), 1e-12f);
        invn_s[tid * 4 + 1] = 1.f / fmaxf(sqrtf(a.y + b.y + c.y + dd.y), 1e-12f);
        invn_s[tid * 4 + 2] = 1.f / fmaxf(sqrtf(a.z + b.z + c.z + dd.z), 1e-12f);
        invn_s[tid * 4 + 3] = 1.f / fmaxf(sqrtf(a.w + b.w + c.w + dd.w), 1e-12f);
    }
    __syncthreads();

    {
        int k = wid * 16 + (lane >> 2);
        float bk0 = bsm[k], bk1 = bsm[k + 8];
#pragma unroll
        for (int g = 0; g < 8; g++) {
            int n = g * 8 + (lane & 3) * 2;
            float i0 = invn_s[n], i1 = invn_s[n + 1];
            *(float2*)&Ls[k * LSS_ + n]       = make_float2(d[g][0] * i0 + bk0, d[g][1] * i1 + bk0);
            *(float2*)&Ls[(k + 8) * LSS_ + n] = make_float2(d[g][2] * i0 + bk1, d[g][3] * i1 + bk1);
        }
    }
    __syncthreads();

    const int col  = tid & 63;
    const int half = tid >> 6;
    float m = -1e30f;
#pragma unroll
    for (int kk = 0; kk < 32; kk++) m = fmaxf(m, Ls[(half * 32 + kk) * LSS_ + col]);
    red[half * 64 + col] = m;
    __syncthreads();
    m = fmaxf(red[col], red[64 + col]);
    __syncthreads();
    float s = 0.f;
#pragma unroll
    for (int kk = 0; kk < 32; kk++) {
        float e = __expf(Ls[(half * 32 + kk) * LSS_ + col] - m);
        Ls[(half * 32 + kk) * LSS_ + col] = e;
        s += e;
    }
    red[half * 64 + col] = s;
    __syncthreads();
    const bool valid = (n0 + col < N_);
    float S    = red[col] + red[64 + col];
    float rinv = valid ? (1.f / S) : 0.f;
    if (half == 0) {
        rinvs[col] = rinv;
        scv[col]   = rinv * invn_s[col];
    }
    __syncthreads();

    {
        int k = tid >> 1, h = tid & 1;
        size_t base = (size_t)(t * K_ + k) * NPAD_ + n0 + h * 32;
#pragma unroll
        for (int j = 0; j < 4; j++) {
            unsigned short hh[8], ll[8];
#pragma unroll
            for (int q = 0; q < 8; q++) {
                int n = h * 32 + j * 8 + q;
                float v = Ls[k * LSS_ + n] * scv[n];
                bsplit(v, hh[q], ll[q]);
            }
            uint4 uh, ul;
            uh.x = hh[0] | ((uint32_t)hh[1] << 16); uh.y = hh[2] | ((uint32_t)hh[3] << 16);
            uh.z = hh[4] | ((uint32_t)hh[5] << 16); uh.w = hh[6] | ((uint32_t)hh[7] << 16);
            ul.x = ll[0] | ((uint32_t)ll[1] << 16); ul.y = ll[2] | ((uint32_t)ll[3] << 16);
            ul.z = ll[4] | ((uint32_t)ll[5] << 16); ul.w = ll[6] | ((uint32_t)ll[7] << 16);
            *(uint4*)&g_ahi[base + j * 8] = uh;
            *(uint4*)&g_alo[base + j * 8] = ul;
        }
    }

    if (tid < 64) {
        float as = 0.f;
#pragma unroll 8
        for (int c2 = 0; c2 < 64; c2++) {
            int cix = (c2 + tid) & 63;
            as += Ls[tid * LSS_ + cix] * rinvs[cix];
        }
        g_asump[((size_t)t * NB_ + blockIdx.x) * K_ + tid] = as;
    }
}

// ---------------- pass 2: VLAD GEMM + fused centroid-subtract + row-sumsq partials ----------------
#define VA_HI 0
#define VA_LO 9216
#define VB_HI 18432
#define VB_LO 36864
#define V_SMEM 55296
__global__ __launch_bounds__(256) void vlad_kernel(
    const float* __restrict__ x, const float* __restrict__ cent)
{
    extern __shared__ char sm[];
    __shared__ float s_as[64];
    __shared__ float s_ss[64][4];
    const int t    = blockIdx.y;
    const int c0   = blockIdx.x * 128;
    const int tid  = threadIdx.x;
    const int wid  = tid >> 5;
    const int lane = tid & 31;
    const int wm   = wid & 1;
    const int wn   = wid >> 1;

    uint32_t sb = (uint32_t)__cvta_generic_to_shared(sm);

    if (tid < 64) {
        float as = 0.f;
#pragma unroll
        for (int b = 0; b < NB_; b++)
            as += g_asump[((size_t)t * NB_ + b) * K_ + tid];
        s_as[tid] = as;
    }

    float d[8][4];
#pragma unroll
    for (int i = 0; i < 8; i++)
#pragma unroll
        for (int j = 0; j < 4; j++) d[i][j] = 0.f;

    const float* xt = x + (size_t)t * C_ * N_;
    const __nv_bfloat16* aht = g_ahi + (size_t)t * K_ * NPAD_;
    const __nv_bfloat16* alt = g_alo + (size_t)t * K_ * NPAD_;

    {
#pragma unroll
        for (int it = 0; it < 4; it++) {
            int e = tid + it * 256;
            int r = e >> 3, g = e & 7;
            int n = g * 8;
            float4 f0 = make_float4(0.f,0.f,0.f,0.f), f1 = f0;
            if (n < N_) {
                f0 = *(const float4*)&xt[(size_t)(c0 + r) * N_ + n];
                f1 = *(const float4*)&xt[(size_t)(c0 + r) * N_ + n + 4];
            }
            float vv[8] = {f0.x,f0.y,f0.z,f0.w,f1.x,f1.y,f1.z,f1.w};
            unsigned short hh[8], ll[8];
#pragma unroll
            for (int q = 0; q < 8; q++) bsplit(vv[q], hh[q], ll[q]);
            uint4 uh, ul;
            uh.x = hh[0] | ((uint32_t)hh[1] << 16); uh.y = hh[2] | ((uint32_t)hh[3] << 16);
            uh.z = hh[4] | ((uint32_t)hh[5] << 16); uh.w = hh[6] | ((uint32_t)hh[7] << 16);
            ul.x = ll[0] | ((uint32_t)ll[1] << 16); ul.y = ll[2] | ((uint32_t)ll[3] << 16);
            ul.z = ll[4] | ((uint32_t)ll[5] << 16); ul.w = ll[6] | ((uint32_t)ll[7] << 16);
            *(uint4*)(sm + VB_HI + r * 144 + g * 16) = uh;
            *(uint4*)(sm + VB_LO + r * 144 + g * 16) = ul;
        }
#pragma unroll
        for (int it = 0; it < 2; it++) {
            int e = tid + it * 256;
            int k = e >> 3, g = e & 7;
            size_t off = (size_t)k * NPAD_ + g * 8;
            *(uint4*)(sm + VA_HI + k * 144 + g * 16) = *(const uint4*)(aht + off);
            *(uint4*)(sm + VA_LO + k * 144 + g * 16) = *(const uint4*)(alt + off);
        }
    }
    __syncthreads();

    for (int ch = 0; ch < 13; ch++) {
        float4 xp[8];
        uint4  aph[2], apl[2];
        if (ch < 12) {
            const int n0 = (ch + 1) * 64;
#pragma unroll
            for (int it = 0; it < 4; it++) {
                int e = tid + it * 256;
                int r = e >> 3, g = e & 7;
                int n = n0 + g * 8;
                xp[it*2] = make_float4(0.f,0.f,0.f,0.f);
                xp[it*2+1] = make_float4(0.f,0.f,0.f,0.f);
                if (n < N_) {
                    xp[it*2]   = *(const float4*)&xt[(size_t)(c0 + r) * N_ + n];
                    xp[it*2+1] = *(const float4*)&xt[(size_t)(c0 + r) * N_ + n + 4];
                }
            }
#pragma unroll
            for (int it = 0; it < 2; it++) {
                int e = tid + it * 256;
                int k = e >> 3, g = e & 7;
                size_t off = (size_t)k * NPAD_ + n0 + g * 8;
                aph[it] = *(const uint4*)(aht + off);
                apl[it] = *(const uint4*)(alt + off);
            }
        }

#pragma unroll
        for (int ks = 0; ks < 4; ks++) {
            uint32_t Ah[2][4], Al[2][4], Bh[2][4], Bl[2][4];
#pragma unroll
            for (int mt = 0; mt < 2; mt++) {
                int row = wm * 32 + mt * 16 + (lane & 15);
                uint32_t coff = (uint32_t)(ks * 16 + (lane >> 4) * 8) * 2;
                uint32_t adr = sb + VA_HI + row * 144 + coff;
                ldm_x4(Ah[mt], adr);
                ldm_x4(Al[mt], adr + (VA_LO - VA_HI));
            }
#pragma unroll
            for (int bp = 0; bp < 2; bp++) {
                int crow = wn * 32 + bp * 16 + ((lane >> 4) << 3) + (lane & 7);
                uint32_t coff = (uint32_t)(ks * 16 + ((lane >> 3) & 1) * 8) * 2;
                uint32_t adr = sb + VB_HI + crow * 144 + coff;
                ldm_x4(Bh[bp], adr);
                ldm_x4(Bl[bp], adr + (VB_LO - VB_HI));
            }
#pragma unroll
            for (int mt = 0; mt < 2; mt++) {
#pragma unroll
                for (int nt = 0; nt < 4; nt++) {
                    int bp = nt >> 1, hp = (nt & 1) * 2;
                    float* dd = d[mt * 4 + nt];
                    mma_bf16(dd, Ah[mt], Bh[bp][hp], Bh[bp][hp + 1]);
                    mma_bf16(dd, Ah[mt], Bl[bp][hp], Bl[bp][hp + 1]);
                    mma_bf16(dd, Al[mt], Bh[bp][hp], Bh[bp][hp + 1]);
                }
            }
        }

        if (ch < 12) {
            __syncthreads();
#pragma unroll
            for (int it = 0; it < 4; it++) {
                int e = tid + it * 256;
                int r = e >> 3, g = e & 7;
                float4 f0 = xp[it*2], f1 = xp[it*2+1];
                float vv[8] = {f0.x,f0.y,f0.z,f0.w,f1.x,f1.y,f1.z,f1.w};
                unsigned short hh[8], ll[8];
#pragma unroll
                for (int q = 0; q < 8; q++) bsplit(vv[q], hh[q], ll[q]);
                uint4 uh, ul;
                uh.x = hh[0] | ((uint32_t)hh[1] << 16); uh.y = hh[2] | ((uint32_t)hh[3] << 16);
                uh.z = hh[4] | ((uint32_t)hh[5] << 16); uh.w = hh[6] | ((uint32_t)hh[7] << 16);
                ul.x = ll[0] | ((uint32_t)ll[1] << 16); ul.y = ll[2] | ((uint32_t)ll[3] << 16);
                ul.z = ll[4] | ((uint32_t)ll[5] << 16); ul.w = ll[6] | ((uint32_t)ll[7] << 16);
                *(uint4*)(sm + VB_HI + r * 144 + g * 16) = uh;
                *(uint4*)(sm + VB_LO + r * 144 + g * 16) = ul;
            }
#pragma unroll
            for (int it = 0; it < 2; it++) {
                int e = tid + it * 256;
                int k = e >> 3, g = e & 7;
                *(uint4*)(sm + VA_HI + k * 144 + g * 16) = aph[it];
                *(uint4*)(sm + VA_LO + k * 144 + g * 16) = apl[it];
            }
            __syncthreads();
        }
    }

    // ---- fused epilogue: v = D - as*cent, store v, per-row sumsq partials ----
    float ssl[2][2] = {{0.f, 0.f}, {0.f, 0.f}};
#pragma unroll
    for (int mt = 0; mt < 2; mt++) {
        int k0r = wm * 32 + mt * 16 + (lane >> 2);
        float as0 = s_as[k0r], as1 = s_as[k0r + 8];
#pragma unroll
        for (int nt = 0; nt < 4; nt++) {
            float* dd = d[mt * 4 + nt];
            int c = c0 + wn * 32 + nt * 8 + (lane & 3) * 2;
            float2 cw0 = *(const float2*)&cent[(size_t)k0r * C_ + c];
            float2 cw1 = *(const float2*)&cent[(size_t)(k0r + 8) * C_ + c];
            float v00 = dd[0] - as0 * cw0.x, v01 = dd[1] - as0 * cw0.y;
            float v10 = dd[2] - as1 * cw1.x, v11 = dd[3] - as1 * cw1.y;
            *(float2*)&g_vlad[(size_t)(t * K_ + k0r) * C_ + c]     = make_float2(v00, v01);
            *(float2*)&g_vlad[(size_t)(t * K_ + k0r + 8) * C_ + c] = make_float2(v10, v11);
            ssl[mt][0] += v00 * v00 + v01 * v01;
            ssl[mt][1] += v10 * v10 + v11 * v11;
        }
    }
#pragma unroll
    for (int mt = 0; mt < 2; mt++) {
#pragma unroll
        for (int hk = 0; hk < 2; hk++) {
            ssl[mt][hk] += __shfl_xor_sync(0xffffffff, ssl[mt][hk], 1);
            ssl[mt][hk] += __shfl_xor_sync(0xffffffff, ssl[mt][hk], 2);
        }
    }
    if ((lane & 3) == 0) {
        int r = lane >> 2;
#pragma unroll
        for (int mt = 0; mt < 2; mt++) {
            int k = wm * 32 + mt * 16 + r;
            s_ss[k][wn]     = ssl[mt][0];
            s_ss[k + 8][wn] = ssl[mt][1];
        }
    }
    __syncthreads();
    if (tid < 64) {
        float ss = s_ss[tid][0] + s_ss[tid][1] + s_ss[tid][2] + s_ss[tid][3];
        g_ssp[(size_t)(t * K_ + tid) * 4 + blockIdx.x] = ss;
    }
}

// ---------------- pass 3: fused parallel scalars + apply + sum over t ----------------
// Each block redundantly (but in parallel across 128 blocks) computes
// A[t,k] = sc*gsc from g_ssp, then out[i] = Σ_t v[t][i]·A[t,k].
__global__ __launch_bounds__(256) void finalize_kernel(float* __restrict__ out) {
    __shared__ float sSc[T_ * K_];     // per-row sc, then A
    __shared__ float sSsn[T_ * K_];    // per-row normalized sumsq
    __shared__ float sPart[T_][8];
    __shared__ float sGsc[T_ + 2];
    const int tid = threadIdx.x;

    // per-row scalars: coalesced float4 loads, 7.5 rows/thread
    for (int i = tid; i < T_ * K_; i += 256) {
        float4 p = *(const float4*)&g_ssp[(size_t)i * 4];
        float ss = p.x + p.y + p.z + p.w;
        float sc = 1.f / fmaxf(sqrtf(ss), 1e-12f);
        sSc[i]  = sc;
        sSsn[i] = ss * sc * sc;
    }
    __syncthreads();
    // per-t reduce: 240 threads, each sums 8 consecutive ssn
    if (tid < T_ * 8) {
        int t = tid >> 3, o = tid & 7;
        float s = 0.f;
#pragma unroll
        for (int q = 0; q < 8; q++) s += sSsn[t * K_ + o * 8 + q];
        sPart[t][o] = s;
    }
    __syncthreads();
    if (tid < T_) {
        float s = sPart[tid][0] + sPart[tid][1] + sPart[tid][2] + sPart[tid][3]
                + sPart[tid][4] + sPart[tid][5] + sPart[tid][6] + sPart[tid][7];
        sGsc[tid] = 1.f / fmaxf(sqrtf(s), 1e-12f);
    }
    __syncthreads();
    for (int i = tid; i < T_ * K_; i += 256)
        sSc[i] *= sGsc[i >> 6];
    __syncthreads();

    const int i = blockIdx.x * 256 + tid;
    const int k = i >> 9;
    float s = 0.f;
#pragma unroll
    for (int t = 0; t < T_; t++)
        s += g_vlad[(size_t)t * KD_ + i] * sSc[t * K_ + k];
    out[i] = s;
}

// ---------------- launch ----------------
extern "C" void kernel_launch(void* const* d_in, const int* in_sizes, int n_in,
                              void* d_out, int out_size) {
    const float* x1     = (const float*)d_in[0];   // [30,512,28,28]
    const float* cent   = (const float*)d_in[1];   // [64,512]
    const float* conv_w = (const float*)d_in[2];   // [64,512]
    const float* conv_b = (const float*)d_in[3];   // [64]
    float* out = (float*)d_out;                    // [1, 32768]

    cudaFuncSetAttribute(assign_kernel, cudaFuncAttributeMaxDynamicSharedMemorySize, A_SMEM);
    cudaFuncSetAttribute(vlad_kernel,   cudaFuncAttributeMaxDynamicSharedMemorySize, V_SMEM);

    prep_kernel<<<128, 256>>>(conv_w);
    {
        dim3 g(NB_, T_);
        assign_kernel<<<g, 128, A_SMEM>>>(x1, conv_b);
    }
    {
        dim3 g(C_ / 128, T_);
        vlad_kernel<<<g, 256, V_SMEM>>>(x1, cent);
    }
    finalize_kernel<<<KD_ / 256, 256>>>(out);
}